// round 14
// baseline (speedup 1.0000x reference)
#include <cuda_runtime.h>
#include <cuda_bf16.h>
#include <cuda_fp16.h>
#include <cstdint>
#include <math.h>

#define BB   16
#define NN   32
#define TDIM 256
#define HH   256
#define EPS  1e-5f

__device__ float  g_h1[BB * NN * HH];                // [512, 256] fp32
__device__ __half g_h2h[BB * TDIM * HH];             // [4096, 256] fp16
__device__ __half g_Bh[256 * 256];                   // W3^T fp16 [n][k]
__device__ __half g_W1h[256 * 512];                  // W1^T fp16 [n][k]
__device__ __half g_W2h[256 * 512];                  // W2^T fp16

__device__ __forceinline__ uint32_t smem_u32(const void* p) {
    uint32_t a;
    asm("{ .reg .u64 t; cvta.to.shared.u64 t, %1; cvt.u32.u64 %0, t; }" : "=r"(a) : "l"(p));
    return a;
}
__device__ __forceinline__ uint32_t pack_f16x2(float lo, float hi) {
    uint32_t r;
    asm("cvt.rn.f16x2.f32 %0, %1, %2;" : "=r"(r) : "f"(hi), "f"(lo));
    return r;
}

#define LDMX4(r, addr) \
    asm volatile("ldmatrix.sync.aligned.m8n8.x4.shared.b16 {%0,%1,%2,%3}, [%4];" \
        : "=r"((r)[0]), "=r"((r)[1]), "=r"((r)[2]), "=r"((r)[3]) : "r"(addr))

#define MMA16816(cc, a, b0, b1) \
    asm volatile("mma.sync.aligned.m16n8k16.row.col.f32.f16.f16.f32 " \
        "{%0,%1,%2,%3}, {%4,%5,%6,%7}, {%8,%9}, {%0,%1,%2,%3};" \
        : "+f"((cc)[0]), "+f"((cc)[1]), "+f"((cc)[2]), "+f"((cc)[3]) \
        : "r"((a)[0]), "r"((a)[1]), "r"((a)[2]), "r"((a)[3]), "r"(b0), "r"(b1))

#define CP_ASYNC16(dst, src) \
    asm volatile("cp.async.cg.shared.global [%0], [%1], 16;" :: "r"(dst), "l"(src))
#define CP_COMMIT() asm volatile("cp.async.commit_group;" ::: "memory")
#define CP_WAIT0()  asm volatile("cp.async.wait_group 0;" ::: "memory")

// ---------------------------------------------------------------------------
// Prep: transpose W1,W2,W3 -> fp16 [n][k].
// ---------------------------------------------------------------------------
__global__ __launch_bounds__(256) void prep_kernel(
    const float* __restrict__ W1, const float* __restrict__ W2,
    const float* __restrict__ W3)
{
    __shared__ float t[32][33];
    const int bid = blockIdx.x;
    const int tid = threadIdx.x;
    const float* W;
    __half* Oh;
    int idx, KK;
    if (bid < 128)      { W = W1; Oh = g_W1h; idx = bid;       KK = 512; }
    else if (bid < 256) { W = W2; Oh = g_W2h; idx = bid - 128; KK = 512; }
    else                { W = W3; Oh = g_Bh;  idx = bid - 256; KK = 256; }

    const int tile_k = idx >> 3, tile_n = idx & 7;
    const int tx = tid & 31, ty = tid >> 5;

#pragma unroll
    for (int i = 0; i < 4; i++)
        t[ty + i * 8][tx] = W[(size_t)(tile_k * 32 + ty + i * 8) * 256 + tile_n * 32 + tx];
    __syncthreads();

#pragma unroll
    for (int i = 0; i < 4; i++) {
        const int nl = ty + i * 8, kl = tx;
        Oh[(size_t)(tile_n * 32 + nl) * KK + tile_k * 32 + kl] = __float2half_rn(t[kl][nl]);
    }
}

// ---------------------------------------------------------------------------
// tc_prologue: h = relu(X @ W + b), single fp16 term.
// Blocks 0-15: h1 (fp32 out). Blocks 16-143: h2 (fp16 out).
// ---------------------------------------------------------------------------
#define PAH 0
#define PBH 32768
#define PBIAS 98304
#define PROLOGUE_SMEM 99360

__global__ __launch_bounds__(512, 1) void tc_prologue(
    const float* __restrict__ x1, const float* __restrict__ b1,
    const float* __restrict__ x2, const float* __restrict__ b2)
{
    extern __shared__ char smem[];
    const uint32_t sb = smem_u32(smem);
    float* bs = (float*)(smem + PBIAS);

    const bool is1 = (blockIdx.x < 16);
    const float* X    = is1 ? x1 : x2;
    const __half* Wh  = is1 ? g_W1h : g_W2h;
    const float* bias = is1 ? b1 : b2;
    const int m0      = (is1 ? blockIdx.x : (blockIdx.x - 16)) * 32;

    const int tid  = threadIdx.x;
    const int lane = tid & 31;
    const int wid  = tid >> 5;

    // chunk 0 -> buf 0
#pragma unroll
    for (int i = 0; i < 4; i++) {
        int seg = tid + i * 512;
        int n = seg >> 3, u = seg & 7;
        CP_ASYNC16(sb + PBH + n * 128 + ((u * 16) ^ ((n & 7) * 16)),
                   (const void*)(Wh + n * 512 + u * 8));
    }
    CP_COMMIT();

    if (tid < 256) bs[tid] = bias[tid];

    // A: X rows -> fp16 swizzled smem
    {
        const int arow = tid >> 4;
        const int k0   = (tid & 15) * 32;
        const float4* xp = (const float4*)(X + (size_t)(m0 + arow) * 512 + k0);
        uint32_t hiu[16];
#pragma unroll
        for (int j = 0; j < 8; j++) {
            float4 v = xp[j];
            hiu[2 * j]     = pack_f16x2(v.x, v.y);
            hiu[2 * j + 1] = pack_f16x2(v.z, v.w);
        }
        const uint32_t rbase = arow * 1024;
        const uint32_t rsw   = (uint32_t)(arow & 7) * 16u;
#pragma unroll
        for (int jj = 0; jj < 4; jj++) {
            uint32_t kbyte = (uint32_t)(k0 * 2 + jj * 16);
            *(uint4*)(smem + PAH + (rbase + (kbyte ^ rsw)))
                = make_uint4(hiu[4*jj], hiu[4*jj+1], hiu[4*jj+2], hiu[4*jj+3]);
        }
    }
    __syncthreads();

    const int wm = wid & 1, wn = wid >> 1;
    const int sub = lane >> 3, r8 = lane & 7;
    const int a_row = wm * 16 + r8 + (sub & 1) * 8;
    const int a_kb  = (sub >> 1) * 16;
    const int b_nrow = wn * 32 + r8 + (sub >> 1) * 8;
    const int b_kb  = (sub & 1) * 16;

    float c[4][4];
#pragma unroll
    for (int nt = 0; nt < 4; nt++)
#pragma unroll
        for (int i = 0; i < 4; i++) c[nt][i] = 0.f;

    for (int ch = 0; ch < 8; ch++) {
        CP_WAIT0();
        __syncthreads();
        if (ch < 7) {
            const int kc2 = (ch + 1) * 64;
            const uint32_t buf = ((ch + 1) & 1) * 32768u;
#pragma unroll
            for (int i = 0; i < 4; i++) {
                int seg = tid + i * 512;
                int n = seg >> 3, u = seg & 7;
                CP_ASYNC16(sb + PBH + buf + n * 128 + ((u * 16) ^ ((n & 7) * 16)),
                           (const void*)(Wh + n * 512 + kc2 + u * 8));
            }
            CP_COMMIT();
        }
        const uint32_t Bh = sb + PBH + (ch & 1) * 32768u;
        const int kcb = ch * 128;

#pragma unroll
        for (int ks = 0; ks < 4; ks++) {
            const int kbyte = ks * 32;
            uint32_t ah[4], bh[2][4];
            {
                uint32_t off = a_row * 1024 + (uint32_t)((kcb + kbyte + a_kb) ^ ((a_row & 7) * 16));
                LDMX4(ah, sb + PAH + off);
            }
#pragma unroll
            for (int nq = 0; nq < 2; nq++) {
                const int nrow = b_nrow + nq * 16;
                uint32_t off = nrow * 128 + (uint32_t)((kbyte + b_kb) ^ ((nrow & 7) * 16));
                LDMX4(bh[nq], Bh + off);
            }
#pragma unroll
            for (int nq = 0; nq < 2; nq++) {
                MMA16816(c[2*nq+0], ah, bh[nq][0], bh[nq][1]);
                MMA16816(c[2*nq+1], ah, bh[nq][2], bh[nq][3]);
            }
        }
    }

    const int row0 = wm * 16 + (lane >> 2);
    const int cb   = wn * 32 + (lane & 3) * 2;
#pragma unroll
    for (int half = 0; half < 2; half++) {
        const int row = row0 + half * 8;
#pragma unroll
        for (int nt = 0; nt < 4; nt++) {
            const int col = cb + nt * 8;
            float v0 = fmaxf(c[nt][half * 2 + 0] + bs[col], 0.f);
            float v1 = fmaxf(c[nt][half * 2 + 1] + bs[col + 1], 0.f);
            if (is1) {
                *(float2*)(g_h1 + (size_t)(m0 + row) * 256 + col) = make_float2(v0, v1);
            } else {
                *(__half2*)(g_h2h + (size_t)(m0 + row) * 256 + col) = __floats2half2_rn(v0, v1);
            }
        }
    }
}

// ---------------------------------------------------------------------------
// Fused PERSISTENT kernel (R12 base): grid 148, 7 tiles/CTA avg.
// h2 now fp16 -> phase-1 reads 1 uint4 per row per lane (halved traffic).
// ---------------------------------------------------------------------------
#define A_OFF 0
#define B_OFF 65536
#define FP_OFF 196608
#define FUSED_SMEM 207872
#define NTILES 1024
#define GRID_F 148

__global__ __launch_bounds__(512, 1) void fused_mma_kernel(
    const float* __restrict__ b3, const float* __restrict__ g0,
    const float* __restrict__ be0, const float* __restrict__ g1,
    const float* __restrict__ be1, float* __restrict__ out)
{
    extern __shared__ char smem[];
    const uint32_t sb = smem_u32(smem);
    float* F   = (float*)(smem + FP_OFF);
    float* h1s = F;          float* b3s = F + 256;
    float* g0s = F + 512;    float* e0s = F + 768;
    float* g1s = F + 1024;   float* e1s = F + 1280;
    float* red_s = F + 1536;   // [128][4]
    float* red_q = F + 2048;   // [128][4]
    float* muS   = F + 2560;   // [128]
    float* invS  = F + 2688;   // [128]

    const int tid  = threadIdx.x;
    const int lane = tid & 31;
    const int wid  = tid >> 5;          // 0..15

    // ---- one-time: B (128KB) + params ----
#pragma unroll
    for (int i = 0; i < 16; i++) {
        int seg = tid + i * 512;
        int n = seg >> 5, u = seg & 31;
        uint32_t dst = sb + B_OFF + n * 512 + (uint32_t)((u * 16) ^ ((n & 7) * 16));
        CP_ASYNC16(dst, (const void*)(g_Bh + n * 256 + u * 8));
    }
    CP_COMMIT();
    if (tid < 256) {
        b3s[tid] = b3[tid];
        g0s[tid] = g0[tid];  e0s[tid] = be0[tid];
        g1s[tid] = g1[tid];  e1s[tid] = be1[tid];
    }

    const int wm = wid & 3, wn = wid >> 2;       // 4m x 4n
    const int sub = lane >> 3, r8 = lane & 7;
    const int a_row = wm * 32 + r8 + (sub & 1) * 8;
    const uint32_t a_kb = (uint32_t)((sub >> 1) * 16);
    const int b_nrow = wn * 64 + r8 + (sub >> 1) * 8;
    const uint32_t b_kb = (uint32_t)((sub & 1) * 16);
    const uint32_t Ab0 = sb + A_OFF + a_row * 512;
    const uint32_t Ab1 = sb + A_OFF + (a_row + 16) * 512;
    const uint32_t asw0 = (uint32_t)(a_row & 7) * 16u;
    const uint32_t asw1 = (uint32_t)((a_row + 16) & 7) * 16u;
    uint32_t Bbs[4], bsw[4];
#pragma unroll
    for (int nq = 0; nq < 4; nq++) {
        const int nrow = b_nrow + nq * 16;
        Bbs[nq] = sb + B_OFF + nrow * 512;
        bsw[nq] = (uint32_t)(nrow & 7) * 16u;
    }
    const int rbase = wm * 32 + (lane >> 2);
    const int cbase = wn * 64 + (lane & 3) * 2;

    int first = 1;

    for (int tile = blockIdx.x; tile < NTILES; tile += GRID_F) {
        const int bn = tile & 511;
        const int b  = bn >> 5;
        const int t0 = (tile >> 9) * 128;

        if (tid < 256) h1s[tid] = g_h1[(size_t)bn * 256 + tid];
        __syncthreads();

        // ---- Phase 1: Hadamard + LN -> A fp16 swizzled (h2 in fp16) ----
#pragma unroll
        for (int rr = 0; rr < 8; rr++) {
            const int r = wid + rr * 16;
            const uint4* h2v = (const uint4*)(g_h2h + ((size_t)(b * TDIM + t0 + r)) * HH) + lane;
            const float4* h1v = (const float4*)h1s + lane * 2;
            float4 a0 = h1v[0], a1 = h1v[1];
            uint4 hv = h2v[0];
            const __half2* hp = (const __half2*)&hv;
            float2 f0 = __half22float2(hp[0]);
            float2 f1 = __half22float2(hp[1]);
            float2 f2 = __half22float2(hp[2]);
            float2 f3 = __half22float2(hp[3]);
            float p[8];
            p[0] = a0.x * f0.x; p[1] = a0.y * f0.y; p[2] = a0.z * f1.x; p[3] = a0.w * f1.y;
            p[4] = a1.x * f2.x; p[5] = a1.y * f2.y; p[6] = a1.z * f3.x; p[7] = a1.w * f3.y;
            float s = 0.f, q = 0.f;
#pragma unroll
            for (int j = 0; j < 8; j++) { s += p[j]; q += p[j] * p[j]; }
#pragma unroll
            for (int o = 16; o > 0; o >>= 1) {
                s += __shfl_xor_sync(0xffffffffu, s, o);
                q += __shfl_xor_sync(0xffffffffu, q, o);
            }
            const float mu  = s * (1.f / 256.f);
            const float var = q * (1.f / 256.f) - mu * mu;
            const float inv = rsqrtf(var + EPS);
            float x[8];
#pragma unroll
            for (int j = 0; j < 8; j++)
                x[j] = (p[j] - mu) * inv * g0s[lane * 8 + j] + e0s[lane * 8 + j];
            uint4 wv;
            wv.x = pack_f16x2(x[0], x[1]); wv.y = pack_f16x2(x[2], x[3]);
            wv.z = pack_f16x2(x[4], x[5]); wv.w = pack_f16x2(x[6], x[7]);
            uint32_t unit = ((uint32_t)(lane * 16)) ^ ((uint32_t)(r & 7) * 16u);
            *(uint4*)(smem + A_OFF + r * 512 + unit) = wv;
        }
        if (first) { CP_WAIT0(); first = 0; }
        __syncthreads();

        // ---- Mainloop: 16 k-steps, fragments double-buffered ----
        float c[2][8][4];
#pragma unroll
        for (int mt = 0; mt < 2; mt++)
#pragma unroll
            for (int nt = 0; nt < 8; nt++)
#pragma unroll
                for (int i = 0; i < 4; i++) c[mt][nt][i] = 0.f;

        uint32_t bq[2][4][4], a[2][2][4];
        {
#pragma unroll
            for (int nq = 0; nq < 4; nq++)
                LDMX4(bq[0][nq], Bbs[nq] + ((b_kb) ^ bsw[nq]));
            LDMX4(a[0][0], Ab0 + ((a_kb) ^ asw0));
            LDMX4(a[0][1], Ab1 + ((a_kb) ^ asw1));
        }

#pragma unroll
        for (int ks = 0; ks < 16; ks++) {
            const int cur = ks & 1, nxt = cur ^ 1;
            if (ks < 15) {
                const uint32_t kb = (uint32_t)((ks + 1) * 32);
#pragma unroll
                for (int nq = 0; nq < 4; nq++)
                    LDMX4(bq[nxt][nq], Bbs[nq] + ((kb + b_kb) ^ bsw[nq]));
                LDMX4(a[nxt][0], Ab0 + ((kb + a_kb) ^ asw0));
                LDMX4(a[nxt][1], Ab1 + ((kb + a_kb) ^ asw1));
            }
#pragma unroll
            for (int mt = 0; mt < 2; mt++)
#pragma unroll
                for (int nq = 0; nq < 4; nq++) {
                    MMA16816(c[mt][2 * nq + 0], a[cur][mt], bq[cur][nq][0], bq[cur][nq][1]);
                    MMA16816(c[mt][2 * nq + 1], a[cur][mt], bq[cur][nq][2], bq[cur][nq][3]);
                }
        }
        __syncthreads();

        // ---- Epilogue: +b3, row LN, relu, store ----
        float s[4], q[4];
#pragma unroll
        for (int mt = 0; mt < 2; mt++)
#pragma unroll
            for (int half = 0; half < 2; half++) {
                float ss = 0.f, qq = 0.f;
#pragma unroll
                for (int nt = 0; nt < 8; nt++) {
                    int col = cbase + nt * 8;
                    float v0 = c[mt][nt][half * 2 + 0] + b3s[col];
                    float v1 = c[mt][nt][half * 2 + 1] + b3s[col + 1];
                    c[mt][nt][half * 2 + 0] = v0;
                    c[mt][nt][half * 2 + 1] = v1;
                    ss += v0 + v1; qq += v0 * v0 + v1 * v1;
                }
                s[mt * 2 + half] = ss; q[mt * 2 + half] = qq;
            }
#pragma unroll
        for (int i = 0; i < 4; i++) {
            s[i] += __shfl_xor_sync(0xffffffffu, s[i], 1);
            s[i] += __shfl_xor_sync(0xffffffffu, s[i], 2);
            q[i] += __shfl_xor_sync(0xffffffffu, q[i], 1);
            q[i] += __shfl_xor_sync(0xffffffffu, q[i], 2);
        }
        if ((lane & 3) == 0) {
#pragma unroll
            for (int mt = 0; mt < 2; mt++)
#pragma unroll
                for (int half = 0; half < 2; half++) {
                    int row = rbase + mt * 16 + half * 8;
                    red_s[row * 4 + wn] = s[mt * 2 + half];
                    red_q[row * 4 + wn] = q[mt * 2 + half];
                }
        }
        __syncthreads();
        if (tid < 128) {
            float ss = red_s[tid * 4] + red_s[tid * 4 + 1] + red_s[tid * 4 + 2] + red_s[tid * 4 + 3];
            float qq = red_q[tid * 4] + red_q[tid * 4 + 1] + red_q[tid * 4 + 2] + red_q[tid * 4 + 3];
            float mu = ss * (1.f / 256.f);
            float var = qq * (1.f / 256.f) - mu * mu;
            muS[tid]  = mu;
            invS[tid] = rsqrtf(var + EPS);
        }
        __syncthreads();

#pragma unroll
        for (int mt = 0; mt < 2; mt++)
#pragma unroll
            for (int half = 0; half < 2; half++) {
                int row = rbase + mt * 16 + half * 8;
                float mu = muS[row], inv = invS[row];
                float2* orow = (float2*)(out + ((size_t)(bn * TDIM + t0 + row)) * HH);
#pragma unroll
                for (int nt = 0; nt < 8; nt++) {
                    int col = cbase + nt * 8;
                    float o0 = fmaxf((c[mt][nt][half * 2 + 0] - mu) * inv * g1s[col] + e1s[col], 0.f);
                    float o1 = fmaxf((c[mt][nt][half * 2 + 1] - mu) * inv * g1s[col + 1] + e1s[col + 1], 0.f);
                    orow[col >> 1] = make_float2(o0, o1);
                }
            }
        __syncthreads();
    }
}

// ---------------------------------------------------------------------------
extern "C" void kernel_launch(void* const* d_in, const int* in_sizes, int n_in,
                              void* d_out, int out_size)
{
    const float* x1  = (const float*)d_in[0];
    const float* x2  = (const float*)d_in[1];
    const float* W1  = (const float*)d_in[2];
    const float* b1  = (const float*)d_in[3];
    const float* W2  = (const float*)d_in[4];
    const float* b2  = (const float*)d_in[5];
    const float* W3  = (const float*)d_in[6];
    const float* b3  = (const float*)d_in[7];
    const float* g0  = (const float*)d_in[8];
    const float* be0 = (const float*)d_in[9];
    const float* g1  = (const float*)d_in[10];
    const float* be1 = (const float*)d_in[11];
    float* out = (float*)d_out;

    static int attr_set = 0;
    if (!attr_set) {
        cudaFuncSetAttribute(fused_mma_kernel,
                             cudaFuncAttributeMaxDynamicSharedMemorySize, FUSED_SMEM);
        cudaFuncSetAttribute(tc_prologue,
                             cudaFuncAttributeMaxDynamicSharedMemorySize, PROLOGUE_SMEM);
        attr_set = 1;
    }

    prep_kernel<<<320, 256>>>(W1, W2, W3);
    tc_prologue<<<144, 512, PROLOGUE_SMEM>>>(x1, b1, x2, b2);

    fused_mma_kernel<<<GRID_F, 512, FUSED_SMEM>>>(b3, g0, be0, g1, be1, out);
}

// round 15
// speedup vs baseline: 1.4640x; 1.4640x over previous
#include <cuda_runtime.h>
#include <cuda_bf16.h>
#include <cuda_fp16.h>
#include <cstdint>
#include <math.h>

#define BB   16
#define NN   32
#define TDIM 256
#define HH   256
#define EPS  1e-5f

__device__ float g_h1[BB * NN * HH];                 // [512, 256]
__device__ float g_h2[BB * TDIM * HH];               // [4096, 256]
__device__ __half g_Bh[256 * 256];                   // W3^T fp16 [n][k]
__device__ __half g_W1h[256 * 512];                  // W1^T fp16 [n][k]
__device__ __half g_W2h[256 * 512];                  // W2^T fp16

__device__ __forceinline__ uint32_t smem_u32(const void* p) {
    uint32_t a;
    asm("{ .reg .u64 t; cvta.to.shared.u64 t, %1; cvt.u32.u64 %0, t; }" : "=r"(a) : "l"(p));
    return a;
}
__device__ __forceinline__ uint32_t pack_f16x2(float lo, float hi) {
    uint32_t r;
    asm("cvt.rn.f16x2.f32 %0, %1, %2;" : "=r"(r) : "f"(hi), "f"(lo));
    return r;
}

#define LDMX4(r, addr) \
    asm volatile("ldmatrix.sync.aligned.m8n8.x4.shared.b16 {%0,%1,%2,%3}, [%4];" \
        : "=r"((r)[0]), "=r"((r)[1]), "=r"((r)[2]), "=r"((r)[3]) : "r"(addr))

#define MMA16816(cc, a, b0, b1) \
    asm volatile("mma.sync.aligned.m16n8k16.row.col.f32.f16.f16.f32 " \
        "{%0,%1,%2,%3}, {%4,%5,%6,%7}, {%8,%9}, {%0,%1,%2,%3};" \
        : "+f"((cc)[0]), "+f"((cc)[1]), "+f"((cc)[2]), "+f"((cc)[3]) \
        : "r"((a)[0]), "r"((a)[1]), "r"((a)[2]), "r"((a)[3]), "r"(b0), "r"(b1))

#define CP_ASYNC16(dst, src) \
    asm volatile("cp.async.cg.shared.global [%0], [%1], 16;" :: "r"(dst), "l"(src))
#define CP_COMMIT() asm volatile("cp.async.commit_group;" ::: "memory")
#define CP_WAIT0()  asm volatile("cp.async.wait_group 0;" ::: "memory")

// ---------------------------------------------------------------------------
// Prep: transpose W1,W2 -> fp16 [n][k]. (W3 handled inside tc_prologue.)
// Blocks 0-127: W1; 128-255: W2.
// ---------------------------------------------------------------------------
__global__ __launch_bounds__(256) void prep_kernel(
    const float* __restrict__ W1, const float* __restrict__ W2)
{
    __shared__ float t[32][33];
    const int bid = blockIdx.x;
    const int tid = threadIdx.x;
    const float* W;
    __half* Oh;
    int idx;
    if (bid < 128) { W = W1; Oh = g_W1h; idx = bid; }
    else           { W = W2; Oh = g_W2h; idx = bid - 128; }

    const int tile_k = idx >> 3, tile_n = idx & 7;
    const int tx = tid & 31, ty = tid >> 5;

#pragma unroll
    for (int i = 0; i < 4; i++)
        t[ty + i * 8][tx] = W[(size_t)(tile_k * 32 + ty + i * 8) * 256 + tile_n * 32 + tx];
    __syncthreads();

#pragma unroll
    for (int i = 0; i < 4; i++) {
        const int nl = ty + i * 8, kl = tx;
        Oh[(size_t)(tile_n * 32 + nl) * 512 + tile_k * 32 + kl] = __float2half_rn(t[kl][nl]);
    }
}

// ---------------------------------------------------------------------------
// tc_prologue: h = relu(X @ W + b), single fp16 term.
// Blocks 0-15: h1. Blocks 16-143: h2. Blocks 144-175: W3 transpose (2 tiles ea).
// ---------------------------------------------------------------------------
#define PAH 0
#define PBH 32768
#define PBIAS 98304
#define PROLOGUE_SMEM 99360

__global__ __launch_bounds__(512, 1) void tc_prologue(
    const float* __restrict__ x1, const float* __restrict__ b1,
    const float* __restrict__ x2, const float* __restrict__ b2,
    const float* __restrict__ W3)
{
    extern __shared__ char smem[];

    if (blockIdx.x >= 144) {
        // W3 [k][n] fp32 -> g_Bh [n][k] fp16. 64 tiles of 32x32; 2 per block.
        float (*t)[32][33] = (float (*)[32][33])smem;
        const int tid  = threadIdx.x;
        const int half = tid >> 8;                  // 0 or 1
        const int lt   = tid & 255;
        const int idx  = (blockIdx.x - 144) * 2 + half;   // 0..63
        const int tile_k = idx >> 3, tile_n = idx & 7;
        const int tx = lt & 31, ty = lt >> 5;
#pragma unroll
        for (int i = 0; i < 4; i++)
            t[half][ty + i * 8][tx] =
                W3[(size_t)(tile_k * 32 + ty + i * 8) * 256 + tile_n * 32 + tx];
        __syncthreads();
#pragma unroll
        for (int i = 0; i < 4; i++) {
            const int nl = ty + i * 8, kl = tx;
            g_Bh[(size_t)(tile_n * 32 + nl) * 256 + tile_k * 32 + kl] =
                __float2half_rn(t[half][kl][nl]);
        }
        return;
    }

    const uint32_t sb = smem_u32(smem);
    float* bs = (float*)(smem + PBIAS);

    const bool is1 = (blockIdx.x < 16);
    const float* X    = is1 ? x1 : x2;
    const __half* Wh  = is1 ? g_W1h : g_W2h;
    const float* bias = is1 ? b1 : b2;
    float* O          = is1 ? g_h1 : g_h2;
    const int m0      = (is1 ? blockIdx.x : (blockIdx.x - 16)) * 32;

    const int tid  = threadIdx.x;
    const int lane = tid & 31;
    const int wid  = tid >> 5;

    // chunk 0 -> buf 0
#pragma unroll
    for (int i = 0; i < 4; i++) {
        int seg = tid + i * 512;
        int n = seg >> 3, u = seg & 7;
        CP_ASYNC16(sb + PBH + n * 128 + ((u * 16) ^ ((n & 7) * 16)),
                   (const void*)(Wh + n * 512 + u * 8));
    }
    CP_COMMIT();

    if (tid < 256) bs[tid] = bias[tid];

    // A: X rows -> fp16 swizzled smem
    {
        const int arow = tid >> 4;
        const int k0   = (tid & 15) * 32;
        const float4* xp = (const float4*)(X + (size_t)(m0 + arow) * 512 + k0);
        uint32_t hiu[16];
#pragma unroll
        for (int j = 0; j < 8; j++) {
            float4 v = xp[j];
            hiu[2 * j]     = pack_f16x2(v.x, v.y);
            hiu[2 * j + 1] = pack_f16x2(v.z, v.w);
        }
        const uint32_t rbase = arow * 1024;
        const uint32_t rsw   = (uint32_t)(arow & 7) * 16u;
#pragma unroll
        for (int jj = 0; jj < 4; jj++) {
            uint32_t kbyte = (uint32_t)(k0 * 2 + jj * 16);
            *(uint4*)(smem + PAH + (rbase + (kbyte ^ rsw)))
                = make_uint4(hiu[4*jj], hiu[4*jj+1], hiu[4*jj+2], hiu[4*jj+3]);
        }
    }
    __syncthreads();

    const int wm = wid & 1, wn = wid >> 1;
    const int sub = lane >> 3, r8 = lane & 7;
    const int a_row = wm * 16 + r8 + (sub & 1) * 8;
    const int a_kb  = (sub >> 1) * 16;
    const int b_nrow = wn * 32 + r8 + (sub >> 1) * 8;
    const int b_kb  = (sub & 1) * 16;

    float c[4][4];
#pragma unroll
    for (int nt = 0; nt < 4; nt++)
#pragma unroll
        for (int i = 0; i < 4; i++) c[nt][i] = 0.f;

    for (int ch = 0; ch < 8; ch++) {
        CP_WAIT0();
        __syncthreads();
        if (ch < 7) {
            const int kc2 = (ch + 1) * 64;
            const uint32_t buf = ((ch + 1) & 1) * 32768u;
#pragma unroll
            for (int i = 0; i < 4; i++) {
                int seg = tid + i * 512;
                int n = seg >> 3, u = seg & 7;
                CP_ASYNC16(sb + PBH + buf + n * 128 + ((u * 16) ^ ((n & 7) * 16)),
                           (const void*)(Wh + n * 512 + kc2 + u * 8));
            }
            CP_COMMIT();
        }
        const uint32_t Bh = sb + PBH + (ch & 1) * 32768u;
        const int kcb = ch * 128;

#pragma unroll
        for (int ks = 0; ks < 4; ks++) {
            const int kbyte = ks * 32;
            uint32_t ah[4], bh[2][4];
            {
                uint32_t off = a_row * 1024 + (uint32_t)((kcb + kbyte + a_kb) ^ ((a_row & 7) * 16));
                LDMX4(ah, sb + PAH + off);
            }
#pragma unroll
            for (int nq = 0; nq < 2; nq++) {
                const int nrow = b_nrow + nq * 16;
                uint32_t off = nrow * 128 + (uint32_t)((kbyte + b_kb) ^ ((nrow & 7) * 16));
                LDMX4(bh[nq], Bh + off);
            }
#pragma unroll
            for (int nq = 0; nq < 2; nq++) {
                MMA16816(c[2*nq+0], ah, bh[nq][0], bh[nq][1]);
                MMA16816(c[2*nq+1], ah, bh[nq][2], bh[nq][3]);
            }
        }
    }

    const int row0 = wm * 16 + (lane >> 2);
    const int cb   = wn * 32 + (lane & 3) * 2;
#pragma unroll
    for (int half = 0; half < 2; half++) {
        const int row = row0 + half * 8;
        float2* orow = (float2*)(O + (size_t)(m0 + row) * 256);
#pragma unroll
        for (int nt = 0; nt < 4; nt++) {
            const int col = cb + nt * 8;
            float v0 = fmaxf(c[nt][half * 2 + 0] + bs[col], 0.f);
            float v1 = fmaxf(c[nt][half * 2 + 1] + bs[col + 1], 0.f);
            orow[col >> 1] = make_float2(v0, v1);
        }
    }
}

// ---------------------------------------------------------------------------
// Fused PERSISTENT kernel (R12 base + h1 double-buffer prefetch).
// Grid 148, ~7 tiles/CTA. Per tile: 128 x 256, K=256, warp tile 32x64.
// B (full W3, 128KB) + params loaded once. h2 fp32 (R12 numerics).
// ---------------------------------------------------------------------------
#define A_OFF 0
#define B_OFF 65536
#define FP_OFF 196608
#define FUSED_SMEM 208896
#define NTILES 1024
#define GRID_F 148

__global__ __launch_bounds__(512, 1) void fused_mma_kernel(
    const float* __restrict__ b3, const float* __restrict__ g0,
    const float* __restrict__ be0, const float* __restrict__ g1,
    const float* __restrict__ be1, float* __restrict__ out)
{
    extern __shared__ char smem[];
    const uint32_t sb = smem_u32(smem);
    float* F   = (float*)(smem + FP_OFF);
    float* h1s = F;            // [2][256] double-buffered
    float* b3s = F + 512;
    float* g0s = F + 768;    float* e0s = F + 1024;
    float* g1s = F + 1280;   float* e1s = F + 1536;
    float* red_s = F + 1792;   // [128][4]
    float* red_q = F + 2304;   // [128][4]
    float* muS   = F + 2816;   // [128]
    float* invS  = F + 2944;   // [128]

    const int tid  = threadIdx.x;
    const int lane = tid & 31;
    const int wid  = tid >> 5;          // 0..15

    // ---- one-time: B (128KB) + params + first h1 ----
#pragma unroll
    for (int i = 0; i < 16; i++) {
        int seg = tid + i * 512;
        int n = seg >> 5, u = seg & 31;
        uint32_t dst = sb + B_OFF + n * 512 + (uint32_t)((u * 16) ^ ((n & 7) * 16));
        CP_ASYNC16(dst, (const void*)(g_Bh + n * 256 + u * 8));
    }
    CP_COMMIT();
    if (tid < 256) {
        b3s[tid] = b3[tid];
        g0s[tid] = g0[tid];  e0s[tid] = be0[tid];
        g1s[tid] = g1[tid];  e1s[tid] = be1[tid];
        if (blockIdx.x < NTILES)
            h1s[tid] = g_h1[(size_t)(blockIdx.x & 511) * 256 + tid];
    }
    __syncthreads();

    const int wm = wid & 3, wn = wid >> 2;       // 4m x 4n
    const int sub = lane >> 3, r8 = lane & 7;
    const int a_row = wm * 32 + r8 + (sub & 1) * 8;
    const uint32_t a_kb = (uint32_t)((sub >> 1) * 16);
    const int b_nrow = wn * 64 + r8 + (sub >> 1) * 8;
    const uint32_t b_kb = (uint32_t)((sub & 1) * 16);
    const uint32_t Ab0 = sb + A_OFF + a_row * 512;
    const uint32_t Ab1 = sb + A_OFF + (a_row + 16) * 512;
    const uint32_t asw0 = (uint32_t)(a_row & 7) * 16u;
    const uint32_t asw1 = (uint32_t)((a_row + 16) & 7) * 16u;
    uint32_t Bbs[4], bsw[4];
#pragma unroll
    for (int nq = 0; nq < 4; nq++) {
        const int nrow = b_nrow + nq * 16;
        Bbs[nq] = sb + B_OFF + nrow * 512;
        bsw[nq] = (uint32_t)(nrow & 7) * 16u;
    }
    const int rbase = wm * 32 + (lane >> 2);
    const int cbase = wn * 64 + (lane & 3) * 2;

    int first = 1;
    int cur = 0;

    for (int tile = blockIdx.x; tile < NTILES; tile += GRID_F) {
        const int bn = tile & 511;
        const int b  = bn >> 5;
        const int t0 = (tile >> 9) * 128;
        const float* h1c = h1s + cur * 256;

        // ---- Phase 1: Hadamard + LN -> A fp16 swizzled (h2 fp32) ----
#pragma unroll
        for (int rr = 0; rr < 8; rr++) {
            const int r = wid + rr * 16;
            const float4* h2v = (const float4*)(g_h2 + ((size_t)(b * TDIM + t0 + r)) * HH) + lane * 2;
            const float4* h1v = (const float4*)h1c + lane * 2;
            float4 a0 = h1v[0], a1 = h1v[1];
            float4 c0 = h2v[0], c1 = h2v[1];
            float p[8];
            p[0] = a0.x * c0.x; p[1] = a0.y * c0.y; p[2] = a0.z * c0.z; p[3] = a0.w * c0.w;
            p[4] = a1.x * c1.x; p[5] = a1.y * c1.y; p[6] = a1.z * c1.z; p[7] = a1.w * c1.w;
            float s = 0.f, q = 0.f;
#pragma unroll
            for (int j = 0; j < 8; j++) { s += p[j]; q += p[j] * p[j]; }
#pragma unroll
            for (int o = 16; o > 0; o >>= 1) {
                s += __shfl_xor_sync(0xffffffffu, s, o);
                q += __shfl_xor_sync(0xffffffffu, q, o);
            }
            const float mu  = s * (1.f / 256.f);
            const float var = q * (1.f / 256.f) - mu * mu;
            const float inv = rsqrtf(var + EPS);
            float x[8];
#pragma unroll
            for (int j = 0; j < 8; j++)
                x[j] = (p[j] - mu) * inv * g0s[lane * 8 + j] + e0s[lane * 8 + j];
            uint4 wv;
            wv.x = pack_f16x2(x[0], x[1]); wv.y = pack_f16x2(x[2], x[3]);
            wv.z = pack_f16x2(x[4], x[5]); wv.w = pack_f16x2(x[6], x[7]);
            uint32_t unit = ((uint32_t)(lane * 16)) ^ ((uint32_t)(r & 7) * 16u);
            *(uint4*)(smem + A_OFF + r * 512 + unit) = wv;
        }
        if (first) { CP_WAIT0(); first = 0; }
        __syncthreads();

        // prefetch next tile's h1 into the other buffer (overlaps mainloop)
        {
            const int ntile = tile + GRID_F;
            if (ntile < NTILES && tid < 256)
                h1s[(cur ^ 1) * 256 + tid] = g_h1[(size_t)(ntile & 511) * 256 + tid];
        }

        // ---- Mainloop: 16 k-steps, fragments double-buffered ----
        float c[2][8][4];
#pragma unroll
        for (int mt = 0; mt < 2; mt++)
#pragma unroll
            for (int nt = 0; nt < 8; nt++)
#pragma unroll
                for (int i = 0; i < 4; i++) c[mt][nt][i] = 0.f;

        uint32_t bq[2][4][4], a[2][2][4];
        {
#pragma unroll
            for (int nq = 0; nq < 4; nq++)
                LDMX4(bq[0][nq], Bbs[nq] + ((b_kb) ^ bsw[nq]));
            LDMX4(a[0][0], Ab0 + ((a_kb) ^ asw0));
            LDMX4(a[0][1], Ab1 + ((a_kb) ^ asw1));
        }

#pragma unroll
        for (int ks = 0; ks < 16; ks++) {
            const int curk = ks & 1, nxt = curk ^ 1;
            if (ks < 15) {
                const uint32_t kb = (uint32_t)((ks + 1) * 32);
#pragma unroll
                for (int nq = 0; nq < 4; nq++)
                    LDMX4(bq[nxt][nq], Bbs[nq] + ((kb + b_kb) ^ bsw[nq]));
                LDMX4(a[nxt][0], Ab0 + ((kb + a_kb) ^ asw0));
                LDMX4(a[nxt][1], Ab1 + ((kb + a_kb) ^ asw1));
            }
#pragma unroll
            for (int mt = 0; mt < 2; mt++)
#pragma unroll
                for (int nq = 0; nq < 4; nq++) {
                    MMA16816(c[mt][2 * nq + 0], a[curk][mt], bq[curk][nq][0], bq[curk][nq][1]);
                    MMA16816(c[mt][2 * nq + 1], a[curk][mt], bq[curk][nq][2], bq[curk][nq][3]);
                }
        }
        __syncthreads();

        // ---- Epilogue: +b3, row LN, relu, store ----
        float s[4], q[4];
#pragma unroll
        for (int mt = 0; mt < 2; mt++)
#pragma unroll
            for (int half = 0; half < 2; half++) {
                float ss = 0.f, qq = 0.f;
#pragma unroll
                for (int nt = 0; nt < 8; nt++) {
                    int col = cbase + nt * 8;
                    float v0 = c[mt][nt][half * 2 + 0] + b3s[col];
                    float v1 = c[mt][nt][half * 2 + 1] + b3s[col + 1];
                    c[mt][nt][half * 2 + 0] = v0;
                    c[mt][nt][half * 2 + 1] = v1;
                    ss += v0 + v1; qq += v0 * v0 + v1 * v1;
                }
                s[mt * 2 + half] = ss; q[mt * 2 + half] = qq;
            }
#pragma unroll
        for (int i = 0; i < 4; i++) {
            s[i] += __shfl_xor_sync(0xffffffffu, s[i], 1);
            s[i] += __shfl_xor_sync(0xffffffffu, s[i], 2);
            q[i] += __shfl_xor_sync(0xffffffffu, q[i], 1);
            q[i] += __shfl_xor_sync(0xffffffffu, q[i], 2);
        }
        if ((lane & 3) == 0) {
#pragma unroll
            for (int mt = 0; mt < 2; mt++)
#pragma unroll
                for (int half = 0; half < 2; half++) {
                    int row = rbase + mt * 16 + half * 8;
                    red_s[row * 4 + wn] = s[mt * 2 + half];
                    red_q[row * 4 + wn] = q[mt * 2 + half];
                }
        }
        __syncthreads();
        if (tid < 128) {
            float ss = red_s[tid * 4] + red_s[tid * 4 + 1] + red_s[tid * 4 + 2] + red_s[tid * 4 + 3];
            float qq = red_q[tid * 4] + red_q[tid * 4 + 1] + red_q[tid * 4 + 2] + red_q[tid * 4 + 3];
            float mu = ss * (1.f / 256.f);
            float var = qq * (1.f / 256.f) - mu * mu;
            muS[tid]  = mu;
            invS[tid] = rsqrtf(var + EPS);
        }
        __syncthreads();

#pragma unroll
        for (int mt = 0; mt < 2; mt++)
#pragma unroll
            for (int half = 0; half < 2; half++) {
                int row = rbase + mt * 16 + half * 8;
                float mu = muS[row], inv = invS[row];
                float2* orow = (float2*)(out + ((size_t)(bn * TDIM + t0 + row)) * HH);
#pragma unroll
                for (int nt = 0; nt < 8; nt++) {
                    int col = cbase + nt * 8;
                    float o0 = fmaxf((c[mt][nt][half * 2 + 0] - mu) * inv * g1s[col] + e1s[col], 0.f);
                    float o1 = fmaxf((c[mt][nt][half * 2 + 1] - mu) * inv * g1s[col + 1] + e1s[col + 1], 0.f);
                    orow[col >> 1] = make_float2(o0, o1);
                }
            }
        __syncthreads();
        cur ^= 1;
    }
}

// ---------------------------------------------------------------------------
extern "C" void kernel_launch(void* const* d_in, const int* in_sizes, int n_in,
                              void* d_out, int out_size)
{
    const float* x1  = (const float*)d_in[0];
    const float* x2  = (const float*)d_in[1];
    const float* W1  = (const float*)d_in[2];
    const float* b1  = (const float*)d_in[3];
    const float* W2  = (const float*)d_in[4];
    const float* b2  = (const float*)d_in[5];
    const float* W3  = (const float*)d_in[6];
    const float* b3  = (const float*)d_in[7];
    const float* g0  = (const float*)d_in[8];
    const float* be0 = (const float*)d_in[9];
    const float* g1  = (const float*)d_in[10];
    const float* be1 = (const float*)d_in[11];
    float* out = (float*)d_out;

    static int attr_set = 0;
    if (!attr_set) {
        cudaFuncSetAttribute(fused_mma_kernel,
                             cudaFuncAttributeMaxDynamicSharedMemorySize, FUSED_SMEM);
        cudaFuncSetAttribute(tc_prologue,
                             cudaFuncAttributeMaxDynamicSharedMemorySize, PROLOGUE_SMEM);
        attr_set = 1;
    }

    prep_kernel<<<256, 256>>>(W1, W2);
    tc_prologue<<<176, 512, PROLOGUE_SMEM>>>(x1, b1, x2, b2, W3);

    fused_mma_kernel<<<GRID_F, 512, FUSED_SMEM>>>(b3, g0, be0, g1, be1, out);
}